// round 1
// baseline (speedup 1.0000x reference)
#include <cuda_runtime.h>

// Problem dims (fixed by the reference):
// B=8, C=1024, T=512, H=W=7 (HW=49), sim_dim D=128, window=101, out_dim=128.

__device__ float g_xm[8u * 1024u * 512u];   // [B, C, T] spatial means (16.8 MB)
__device__ float g_y [8u * 512u * 128u];    // [B*T, 128] normalized projections (2 MB)

// ---------------------------------------------------------------------------
// Kernel 1: spatial mean over H*W=49.
// One warp per (b,c,t) triple; warp g reads the 49 contiguous floats at g*49.
// xm stored in [B,C,T] layout => xm[g], coalesced via smem staging.
// ---------------------------------------------------------------------------
__global__ void __launch_bounds__(256) k_mean(const float* __restrict__ in) {
    int tid  = threadIdx.x;
    int lane = tid & 31;
    int wid  = tid >> 5;
    size_t g = (size_t)blockIdx.x * 8 + wid;          // 0 .. 4194303
    size_t base = g * 49;

    float s = in[base + lane];
    if (lane < 17) s += in[base + lane + 32];
    #pragma unroll
    for (int o = 16; o; o >>= 1) s += __shfl_xor_sync(0xffffffffu, s, o);

    __shared__ float sh[8];
    if (lane == 0) sh[wid] = s * (1.0f / 49.0f);
    __syncthreads();
    if (tid < 8) g_xm[(size_t)blockIdx.x * 8 + tid] = sh[tid];
}

// ---------------------------------------------------------------------------
// Kernel 2: projection GEMM + bias + L2 normalize.
// A = g_xm viewed as A[m=(b,t)][k=c] at  b*524288 + k*512 + t   (K-major)
// B = proj_w [1024,128] row-major.  Tile: 32 rows x 128 cols, BK=16.
// 256 threads; thread (ty=tid/32, tx=tid%32) owns rows ty*4..+3, cols tx*4..+3.
// Warp == 4 consecutive rows -> butterfly sum-of-squares for the L2 norm.
// ---------------------------------------------------------------------------
__global__ void __launch_bounds__(256) k_proj(const float* __restrict__ pw,
                                              const float* __restrict__ pb) {
    __shared__ __align__(16) float As[16][32];
    __shared__ __align__(16) float Bs[16][128];

    int tid = threadIdx.x;
    int tx  = tid & 31;
    int ty  = tid >> 5;
    int m0  = blockIdx.x * 32;          // row tile start (aligned: 512 % 32 == 0)
    int b   = m0 >> 9;
    int t0  = m0 & 511;
    const float* Abase = g_xm + (size_t)b * 524288 + t0;
    const float4* pw4 = (const float4*)pw;

    float4 acc[4];
    acc[0] = acc[1] = acc[2] = acc[3] = make_float4(0.f, 0.f, 0.f, 0.f);

    for (int k0 = 0; k0 < 1024; k0 += 16) {
        // A tile: 16 k x 32 m, coalesced (32 contiguous floats per k)
        As[ty][tx]     = Abase[(size_t)(k0 + ty)     * 512 + tx];
        As[ty + 8][tx] = Abase[(size_t)(k0 + ty + 8) * 512 + tx];
        // B tile: 16 k x 128 n as 512 float4s
        {
            int i0 = tid, i1 = tid + 256;
            ((float4*)Bs)[i0] = pw4[(size_t)(k0 + (i0 >> 5)) * 32 + (i0 & 31)];
            ((float4*)Bs)[i1] = pw4[(size_t)(k0 + (i1 >> 5)) * 32 + (i1 & 31)];
        }
        __syncthreads();

        #pragma unroll
        for (int k = 0; k < 16; k++) {
            float4 a  = ((const float4*)As[k])[ty];   // 4 rows' A values (broadcast)
            float4 bb = ((const float4*)Bs[k])[tx];   // 4 cols' B values
            acc[0].x += a.x * bb.x; acc[0].y += a.x * bb.y; acc[0].z += a.x * bb.z; acc[0].w += a.x * bb.w;
            acc[1].x += a.y * bb.x; acc[1].y += a.y * bb.y; acc[1].z += a.y * bb.z; acc[1].w += a.y * bb.w;
            acc[2].x += a.z * bb.x; acc[2].y += a.z * bb.y; acc[2].z += a.z * bb.z; acc[2].w += a.z * bb.w;
            acc[3].x += a.w * bb.x; acc[3].y += a.w * bb.y; acc[3].z += a.w * bb.z; acc[3].w += a.w * bb.w;
        }
        __syncthreads();
    }

    float4 bias = ((const float4*)pb)[tx];
    #pragma unroll
    for (int rr = 0; rr < 4; rr++) {
        float4 v = acc[rr];
        v.x += bias.x; v.y += bias.y; v.z += bias.z; v.w += bias.w;
        float ss = v.x * v.x + v.y * v.y + v.z * v.z + v.w * v.w;
        #pragma unroll
        for (int o = 16; o; o >>= 1) ss += __shfl_xor_sync(0xffffffffu, ss, o);
        float inv = 1.0f / fmaxf(sqrtf(ss), 1e-12f);
        v.x *= inv; v.y *= inv; v.z *= inv; v.w *= inv;
        ((float4*)g_y)[(size_t)(m0 + ty * 4 + rr) * 32 + tx] = v;
    }
}

// ---------------------------------------------------------------------------
// Kernel 3: banded cosine-sim + fc + ReLU, fused.
// One warp per (b,t). Lane holds q = y[row][4l..4l+3]; for each in-range w:
// dot via butterfly, then acc += dot * fc_w[w][4l..4l+3]. Bias preloaded.
// ---------------------------------------------------------------------------
__global__ void __launch_bounds__(256) k_band_fc(const float* __restrict__ fw,
                                                 const float* __restrict__ fb,
                                                 float* __restrict__ out) {
    int tid  = threadIdx.x;
    int lane = tid & 31;
    int row  = (blockIdx.x * 256 + tid) >> 5;   // row = b*512 + t, 0..4095
    int t    = row & 511;

    const float4* y4  = (const float4*)g_y;
    const float4* fw4 = (const float4*)fw;
    float4 q   = y4[(size_t)row * 32 + lane];
    float4 acc = ((const float4*)fb)[lane];

    int w0 = (t < 50)  ? (50 - t)  : 0;          // first in-range w
    int w1 = (562 - t < 101) ? (562 - t) : 101;  // one past last in-range w

    for (int w = w0; w < w1; w++) {
        long long nrow = (long long)row + (w - 50);   // same b guaranteed by bounds
        float4 kv = y4[nrow * 32 + lane];
        float p = q.x * kv.x + q.y * kv.y + q.z * kv.z + q.w * kv.w;
        #pragma unroll
        for (int o = 16; o; o >>= 1) p += __shfl_xor_sync(0xffffffffu, p, o);
        float4 fwv = fw4[w * 32 + lane];
        acc.x += p * fwv.x; acc.y += p * fwv.y; acc.z += p * fwv.z; acc.w += p * fwv.w;
    }

    acc.x = fmaxf(acc.x, 0.f);
    acc.y = fmaxf(acc.y, 0.f);
    acc.z = fmaxf(acc.z, 0.f);
    acc.w = fmaxf(acc.w, 0.f);
    ((float4*)out)[(size_t)row * 32 + lane] = acc;
}

// ---------------------------------------------------------------------------
extern "C" void kernel_launch(void* const* d_in, const int* in_sizes, int n_in,
                              void* d_out, int out_size) {
    const float* in = (const float*)d_in[0];   // [8,1024,512,7,7]
    const float* pw = (const float*)d_in[1];   // [1024,128]
    const float* pb = (const float*)d_in[2];   // [128]
    const float* fw = (const float*)d_in[3];   // [101,128]
    const float* fb = (const float*)d_in[4];   // [128]
    float* out = (float*)d_out;                // [8,512,128]

    k_mean<<<524288, 256>>>(in);               // 4.19M warps, 1 per (b,c,t)
    k_proj<<<128, 256>>>(pw, pb);              // 128 row-tiles of 32
    k_band_fc<<<512, 256>>>(fw, fb, out);      // 4096 warps, 1 per (b,t)
}

// round 2
// speedup vs baseline: 1.9240x; 1.9240x over previous
#include <cuda_runtime.h>

// Problem dims (fixed by the reference):
// B=8, C=1024, T=512, H=W=7 (HW=49), sim_dim D=128, window=101, out_dim=128.

__device__ float g_xm[8u * 1024u * 512u];   // [B, C, T] spatial means (16.8 MB)
__device__ float g_y [8u * 512u * 128u];    // [B*T, 128] normalized projections (2 MB)

// ---------------------------------------------------------------------------
// Kernel 1: spatial mean over H*W=49 — streaming + smem transpose.
// Block handles 128 consecutive flattened (b,c,t) rows = 25088 contiguous
// floats. Fully-coalesced float4 loads into smem; then 128 threads each sum
// 49 smem floats (stride 49 mod 32 = 17 -> conflict-free) and write 128
// contiguous outputs. No shuffles, no misaligned global reads.
// ---------------------------------------------------------------------------
__global__ void __launch_bounds__(256) k_mean(const float* __restrict__ in) {
    __shared__ __align__(16) float s[128 * 49];     // 25088 B
    const float4* in4 = (const float4*)in;
    float4* s4 = (float4*)s;
    size_t base4 = (size_t)blockIdx.x * 1568;       // 128*49/4 float4s per block

    #pragma unroll
    for (int i = 0; i < 6; i++) {
        int j = threadIdx.x + i * 256;
        s4[j] = in4[base4 + j];
    }
    {   // tail: 1568 = 6*256 + 32
        int j = threadIdx.x + 1536;
        if (j < 1568) s4[j] = in4[base4 + j];
    }
    __syncthreads();

    if (threadIdx.x < 128) {
        const float* p = s + threadIdx.x * 49;
        float acc = 0.f;
        #pragma unroll
        for (int i = 0; i < 49; i++) acc += p[i];
        g_xm[(size_t)blockIdx.x * 128 + threadIdx.x] = acc * (1.0f / 49.0f);
    }
}

// ---------------------------------------------------------------------------
// Kernel 2: projection GEMM + bias + L2 normalize.
// A = g_xm viewed as A[m=(b,t)][k=c] at  b*524288 + k*512 + t   (K-major)
// B = proj_w [1024,128] row-major.  Tile: 16 rows x 128 cols, BK=16.
// 256 threads; thread (ty=tid/32, tx=tid%32) owns rows ty*2..+1, cols tx*4..+3.
// grid = 256 blocks (~2/SM) for latency hiding. Warp = 2 complete rows ->
// butterfly sum-of-squares for the L2 norm works per row.
// ---------------------------------------------------------------------------
__global__ void __launch_bounds__(256) k_proj(const float* __restrict__ pw,
                                              const float* __restrict__ pb) {
    __shared__ __align__(16) float As[16][16];
    __shared__ __align__(16) float Bs[16][128];

    int tid = threadIdx.x;
    int tx  = tid & 31;
    int ty  = tid >> 5;
    int m0  = blockIdx.x * 16;          // row tile start (512 % 16 == 0)
    int b   = m0 >> 9;
    int t0  = m0 & 511;
    const float* Abase = g_xm + (size_t)b * 524288 + t0;
    const float4* pw4 = (const float4*)pw;

    int akk = tid >> 4;                 // 0..15 (k within tile)
    int amm = tid & 15;                 // 0..15 (m within tile)

    float4 acc[2];
    acc[0] = acc[1] = make_float4(0.f, 0.f, 0.f, 0.f);

    for (int k0 = 0; k0 < 1024; k0 += 16) {
        As[akk][amm] = Abase[(size_t)(k0 + akk) * 512 + amm];
        {
            int i0 = tid, i1 = tid + 256;
            ((float4*)Bs)[i0] = pw4[(size_t)(k0 + (i0 >> 5)) * 32 + (i0 & 31)];
            ((float4*)Bs)[i1] = pw4[(size_t)(k0 + (i1 >> 5)) * 32 + (i1 & 31)];
        }
        __syncthreads();

        #pragma unroll
        for (int k = 0; k < 16; k++) {
            float a0 = As[k][ty * 2 + 0];
            float a1 = As[k][ty * 2 + 1];
            float4 bb = ((const float4*)Bs[k])[tx];
            acc[0].x += a0 * bb.x; acc[0].y += a0 * bb.y; acc[0].z += a0 * bb.z; acc[0].w += a0 * bb.w;
            acc[1].x += a1 * bb.x; acc[1].y += a1 * bb.y; acc[1].z += a1 * bb.z; acc[1].w += a1 * bb.w;
        }
        __syncthreads();
    }

    float4 bias = ((const float4*)pb)[tx];
    #pragma unroll
    for (int rr = 0; rr < 2; rr++) {
        float4 v = acc[rr];
        v.x += bias.x; v.y += bias.y; v.z += bias.z; v.w += bias.w;
        float ss = v.x * v.x + v.y * v.y + v.z * v.z + v.w * v.w;
        #pragma unroll
        for (int o = 16; o; o >>= 1) ss += __shfl_xor_sync(0xffffffffu, ss, o);
        float inv = 1.0f / fmaxf(sqrtf(ss), 1e-12f);
        v.x *= inv; v.y *= inv; v.z *= inv; v.w *= inv;
        ((float4*)g_y)[(size_t)(m0 + ty * 2 + rr) * 32 + tx] = v;
    }
}

// ---------------------------------------------------------------------------
// Kernel 3: banded cosine-sim + fc + ReLU, fused.
// One warp per (b,t). Lane holds q = y[row][4l..4l+3]; for each in-range w:
// dot via butterfly, then acc += dot * fc_w[w][4l..4l+3]. Bias preloaded.
// ---------------------------------------------------------------------------
__global__ void __launch_bounds__(256) k_band_fc(const float* __restrict__ fw,
                                                 const float* __restrict__ fb,
                                                 float* __restrict__ out) {
    int tid  = threadIdx.x;
    int lane = tid & 31;
    int row  = (blockIdx.x * 256 + tid) >> 5;   // row = b*512 + t, 0..4095
    int t    = row & 511;

    const float4* y4  = (const float4*)g_y;
    const float4* fw4 = (const float4*)fw;
    float4 q   = y4[(size_t)row * 32 + lane];
    float4 acc = ((const float4*)fb)[lane];

    int w0 = (t < 50)  ? (50 - t)  : 0;          // first in-range w
    int w1 = (562 - t < 101) ? (562 - t) : 101;  // one past last in-range w

    for (int w = w0; w < w1; w++) {
        long long nrow = (long long)row + (w - 50);   // same b guaranteed by bounds
        float4 kv = y4[nrow * 32 + lane];
        float p = q.x * kv.x + q.y * kv.y + q.z * kv.z + q.w * kv.w;
        #pragma unroll
        for (int o = 16; o; o >>= 1) p += __shfl_xor_sync(0xffffffffu, p, o);
        float4 fwv = fw4[w * 32 + lane];
        acc.x += p * fwv.x; acc.y += p * fwv.y; acc.z += p * fwv.z; acc.w += p * fwv.w;
    }

    acc.x = fmaxf(acc.x, 0.f);
    acc.y = fmaxf(acc.y, 0.f);
    acc.z = fmaxf(acc.z, 0.f);
    acc.w = fmaxf(acc.w, 0.f);
    ((float4*)out)[(size_t)row * 32 + lane] = acc;
}

// ---------------------------------------------------------------------------
extern "C" void kernel_launch(void* const* d_in, const int* in_sizes, int n_in,
                              void* d_out, int out_size) {
    const float* in = (const float*)d_in[0];   // [8,1024,512,7,7]
    const float* pw = (const float*)d_in[1];   // [1024,128]
    const float* pb = (const float*)d_in[2];   // [128]
    const float* fw = (const float*)d_in[3];   // [101,128]
    const float* fb = (const float*)d_in[4];   // [128]
    float* out = (float*)d_out;                // [8,512,128]

    k_mean<<<32768, 256>>>(in);                // block = 128 (b,c,t) rows
    k_proj<<<256, 256>>>(pw, pb);              // 256 row-tiles of 16
    k_band_fc<<<512, 256>>>(fw, fb, out);      // 4096 warps, 1 per (b,t)
}